// round 6
// baseline (speedup 1.0000x reference)
#include <cuda_runtime.h>
#include <math.h>
#include <float.h>

typedef unsigned long long ull;

#define NPIX (32*32*1024)
#define Vv 4096

// ---- static device scratch ----
__device__ float g_frest[NPIX];
__device__ float g_h32[NPIX];
__device__ float g_hits[Vv];
__device__ float g_esq[Vv];
__device__ float g_Mm[5][32][16];
__device__ float g_part[1024];
__device__ ull   g_best[32768];
__device__ unsigned g_ctr = 0;
__device__ unsigned g_gen = 0;

// ---- packed f32x2 helpers ----
__device__ __forceinline__ ull pack2(float lo, float hi) {
    ull d;
    asm("mov.b64 %0, {%1, %2};" : "=l"(d)
        : "r"(__float_as_uint(lo)), "r"(__float_as_uint(hi)));
    return d;
}
__device__ __forceinline__ float2 unpack2(ull v) {
    unsigned int lo, hi;
    asm("mov.b64 {%0, %1}, %2;" : "=r"(lo), "=r"(hi) : "l"(v));
    return make_float2(__uint_as_float(lo), __uint_as_float(hi));
}
__device__ __forceinline__ ull fma2(ull a, ull b, ull c) {
    ull d;
    asm("fma.rn.f32x2 %0, %1, %2, %3;" : "=l"(d) : "l"(a), "l"(b), "l"(c));
    return d;
}
__device__ __forceinline__ ull add2(ull a, ull b) {
    ull d;
    asm("add.rn.f32x2 %0, %1, %2;" : "=l"(d) : "l"(a), "l"(b));
    return d;
}

// ---- grid-wide barrier (all blocks resident; sense-reversing) ----
__device__ __forceinline__ void gridbar(int NB) {
    __syncthreads();
    if (threadIdx.x == 0) {
        __threadfence();                         // order my writes + L1D IVALL
        unsigned gen = *((volatile unsigned*)&g_gen);
        if (atomicAdd(&g_ctr, 1u) == (unsigned)(NB - 1)) {
            *((volatile unsigned*)&g_ctr) = 0u;
            __threadfence();
            atomicAdd(&g_gen, 1u);
        } else {
            while (*((volatile unsigned*)&g_gen) == gen) __nanosleep(64);
        }
        __threadfence();                         // invalidate L1 before fresh reads
    }
    __syncthreads();
}

__device__ __forceinline__ ull enc_key(float d, int idx) {
    unsigned u = __float_as_uint(d);
    u = (u & 0x80000000u) ? ~u : (u | 0x80000000u);
    return ((ull)u << 12) | (unsigned)idx;
}

#define PHI_CI 1224   // 34*36 padded channel plane

extern "C" __global__ void __launch_bounds__(256, 2)
mega(const float4* __restrict__ f, const float* __restrict__ emb,
     const float* __restrict__ pw, const float* __restrict__ pb,
     float* __restrict__ out, int out_size, int NB)
{
    extern __shared__ float sm[];
    int t = threadIdx.x, blk = blockIdx.x;

    // ================= phase 0: prep =================
    {
        float s = 0.f;
        float4* out4 = (float4*)out;
        for (int i = blk*256 + t; i < NPIX/4; i += NB*256) {
            float4 v = f[i];
            ((float4*)g_frest)[i] = v;
            s = fmaf(v.x, v.x, fmaf(v.y, v.y, fmaf(v.z, v.z, fmaf(v.w, v.w, s))));
            out4[i] = make_float4(0.f, 0.f, 0.f, 0.f);
        }
        sm[t] = s; __syncthreads();
        for (int o = 128; o > 0; o >>= 1) { if (t < o) sm[t] += sm[t+o]; __syncthreads(); }
        if (t == 0) g_part[blk] = sm[0];

        for (int v = blk*256 + t; v < Vv; v += NB*256) {
            g_hits[v] = 0.f;
            const float* e = emb + v*32;
            float acc = 0.f;
            #pragma unroll
            for (int c = 0; c < 32; c++) acc += e[c]*e[c];
            g_esq[v] = acc;
        }
        for (int i = blk*256 + t; i < 160; i += NB*256) {
            int si = i >> 5, r = i & 31;
            const int pns5[5] = {1,2,4,8,16};
            int pn = pns5[si];
            for (int j = 0; j < 16; j++) g_Mm[si][r][j] = 0.f;
            double scale = (double)pn / 32.0;
            double x = (r + 0.5)*scale - 0.5;
            double x0 = floor(x);
            double tt = x - x0;
            int ix0 = (int)x0;
            const double a = -0.75;
            for (int j = -1; j <= 2; j++) {
                double d = fabs(tt - (double)j);
                double w;
                if (d < 1.0)      w = (a+2.0)*d*d*d - (a+3.0)*d*d + 1.0;
                else if (d < 2.0) w = a*d*d*d - 5.0*a*d*d + 8.0*a*d - 4.0*a;
                else              w = 0.0;
                int col = ix0 + j;
                col = col < 0 ? 0 : (col > pn-1 ? pn-1 : col);
                g_Mm[si][r][col] = (float)((double)g_Mm[si][r][col] + w);
            }
        }
        for (int i = blk*256 + t; i < 32; i += NB*256) g_best[i] = ~0ull;  // si=0
    }
    gridbar(NB);

    const int pns[6]    = {1,2,4,8,16,32};
    const int VSs[6]    = {8,16,8,8,2,1};
    const int phiSel[6] = {0,0,1,2,3,3};

    for (int si = 0; si < 6; si++) {
        int pn = pns[si], pnpn = pn*pn, N = 32*pnpn, VS = VSs[si];
        int chunk = 4096 / VS;
        int TC = chunk < 512 ? chunk : 512;
        int s = 32 / pn;
        float inv = 1.f / (float)(s*s);

        // smem layout for argmin
        float4* es4  = (float4*)sm;
        float*  esq_s = sm + (size_t)TC*32;
        ull*    z2t  = (ull*)(sm + (size_t)TC*33);   // up to 16*64
        float*  sdA  = (float*)(z2t + 1024);
        float*  sdB  = sdA + 256;
        int*    svA  = (int*)(sdB + 256);
        int*    svB  = svA + 256;

        // ============ argmin (fused area-downsample) ============
        if (pn == 1) {
            // 32 rows per item
            int items = VS;  // G = 1
            for (int item = blk; item < items; item += NB) {
                __syncthreads();
                int vc = item;
                {   // z: thread t -> row t>>3, channels (t&7)*4..+3
                    int r = t >> 3, cq = (t & 7)*4;
                    int b = r;  // pnpn=1: n=r, b=r, p=0
                    float zc[4];
                    #pragma unroll
                    for (int q = 0; q < 4; q++) {
                        const float* base = g_frest + (((b<<5) + cq + q) << 10);
                        float acc = 0.f;
                        for (int dy = 0; dy < 32; dy++) {
                            const float* bp = base + dy*32;
                            for (int dx = 0; dx < 32; dx++) acc += __ldcg(bp + dx);
                        }
                        zc[q] = acc * inv;
                    }
                    int i0 = cq >> 1;
                    z2t[i0*32 + r]     = pack2(zc[0], zc[1]);
                    z2t[(i0+1)*32 + r] = pack2(zc[2], zc[3]);
                }
                __syncthreads();
                int w = t >> 5, l = t & 31;
                ull zp[16];
                #pragma unroll
                for (int i = 0; i < 16; i++) zp[i] = z2t[i*32 + l];
                float best = FLT_MAX; int bv = 0;
                int v0 = vc*chunk;
                for (int t0 = v0; t0 < v0 + chunk; t0 += TC) {
                    __syncthreads();
                    const float4* eg = (const float4*)(emb + (size_t)t0*32);
                    for (int i = t; i < TC*8; i += 256) es4[i] = eg[i];
                    for (int i = t; i < TC;   i += 256) esq_s[i] = g_esq[t0 + i];
                    __syncthreads();
                    for (int v = w; v < TC; v += 8) {
                        const ulonglong2* evp = (const ulonglong2*)(es4 + v*8);
                        ull a0 = 0ull, a1 = 0ull;
                        #pragma unroll
                        for (int i = 0; i < 8; i++) {
                            ulonglong2 q = evp[i];
                            a0 = fma2(zp[2*i],   q.x, a0);
                            a1 = fma2(zp[2*i+1], q.y, a1);
                        }
                        float2 pq = unpack2(add2(a0, a1));
                        float dist = fmaf(-2.f, pq.x + pq.y, esq_s[v]);
                        if (dist < best) { best = dist; bv = t0 + v; }
                    }
                }
                sdA[t] = best; svA[t] = bv;
                __syncthreads();
                if (w == 0) {
                    float bb = sdA[l]; int vv = svA[l];
                    #pragma unroll
                    for (int k = 1; k < 8; k++) {
                        float d2 = sdA[k*32 + l]; int v2 = svA[k*32 + l];
                        if (d2 < bb || (d2 == bb && v2 < vv)) { bb = d2; vv = v2; }
                    }
                    atomicMin(&g_best[l], enc_key(bb, vv));
                }
            }
        } else {
            // 64 rows per item
            int G = N / 64;
            int items = G * VS;
            for (int item = blk; item < items; item += NB) {
                __syncthreads();
                int g = item % G, vc = item / G;
                {   // z: thread t -> row t>>2 (0..63), channels (t&3)*8..+7
                    int r = t >> 2, cq = (t & 3)*8;
                    int n = g*64 + r;
                    int b = n / pnpn, p = n - b*pnpn;
                    int ph = p / pn, pwv = p - ph*pn;
                    float zc[8];
                    #pragma unroll
                    for (int q = 0; q < 8; q++) {
                        const float* base = g_frest + (((b<<5) + cq + q) << 10)
                                          + (ph*s)*32 + pwv*s;
                        float acc = 0.f;
                        for (int dy = 0; dy < s; dy++) {
                            const float* bp = base + dy*32;
                            for (int dx = 0; dx < s; dx++) acc += __ldcg(bp + dx);
                        }
                        zc[q] = acc * inv;
                    }
                    int i0 = cq >> 1;
                    #pragma unroll
                    for (int j = 0; j < 4; j++)
                        z2t[(i0+j)*64 + r] = pack2(zc[2*j], zc[2*j+1]);
                }
                __syncthreads();
                int w = t >> 5, l = t & 31;
                ull zpA[16], zpB[16];
                #pragma unroll
                for (int i = 0; i < 16; i++) {
                    zpA[i] = z2t[i*64 + l];
                    zpB[i] = z2t[i*64 + 32 + l];
                }
                float bestA = FLT_MAX, bestB = FLT_MAX; int bvA = 0, bvB = 0;
                int v0 = vc*chunk;
                for (int t0 = v0; t0 < v0 + chunk; t0 += TC) {
                    __syncthreads();
                    const float4* eg = (const float4*)(emb + (size_t)t0*32);
                    for (int i = t; i < TC*8; i += 256) es4[i] = eg[i];
                    for (int i = t; i < TC;   i += 256) esq_s[i] = g_esq[t0 + i];
                    __syncthreads();
                    for (int v = w; v < TC; v += 8) {
                        const ulonglong2* evp = (const ulonglong2*)(es4 + v*8);
                        ull a0 = 0ull, a1 = 0ull, b0 = 0ull, b1 = 0ull;
                        #pragma unroll
                        for (int i = 0; i < 8; i++) {
                            ulonglong2 q = evp[i];
                            a0 = fma2(zpA[2*i],   q.x, a0);
                            a1 = fma2(zpA[2*i+1], q.y, a1);
                            b0 = fma2(zpB[2*i],   q.x, b0);
                            b1 = fma2(zpB[2*i+1], q.y, b1);
                        }
                        float2 pa = unpack2(add2(a0, a1));
                        float dA = fmaf(-2.f, pa.x + pa.y, esq_s[v]);
                        float2 pbv = unpack2(add2(b0, b1));
                        float dB = fmaf(-2.f, pbv.x + pbv.y, esq_s[v]);
                        if (dA < bestA) { bestA = dA; bvA = t0 + v; }
                        if (dB < bestB) { bestB = dB; bvB = t0 + v; }
                    }
                }
                sdA[t] = bestA; svA[t] = bvA; sdB[t] = bestB; svB[t] = bvB;
                __syncthreads();
                int w2i = t >> 5, l2 = t & 31;
                if (w2i == 0) {
                    float bb = sdA[l2]; int vv = svA[l2];
                    #pragma unroll
                    for (int k = 1; k < 8; k++) {
                        float d2 = sdA[k*32 + l2]; int v2 = svA[k*32 + l2];
                        if (d2 < bb || (d2 == bb && v2 < vv)) { bb = d2; vv = v2; }
                    }
                    atomicMin(&g_best[g*64 + l2], enc_key(bb, vv));
                } else if (w2i == 1) {
                    float bb = sdB[l2]; int vv = svB[l2];
                    #pragma unroll
                    for (int k = 1; k < 8; k++) {
                        float d2 = sdB[k*32 + l2]; int v2 = svB[k*32 + l2];
                        if (d2 < bb || (d2 == bb && v2 < vv)) { bb = d2; vv = v2; }
                    }
                    atomicMin(&g_best[g*64 + 32 + l2], enc_key(bb, vv));
                }
            }
        }
        gridbar(NB);

        if (si < 5) {
            // ============ ups (+hits) ============
            {
                float* hq  = sm;
                float* tmp = hq + 4*pnpn;
                float* Ms  = tmp + 4*pn*32;
                for (int item = blk; item < 256; item += NB) {
                    __syncthreads();
                    int b = item >> 3, cg = item & 7;
                    for (int i = t; i < 32*pn; i += 256) Ms[i] = g_Mm[si][i/pn][i%pn];
                    if (cg == 0) {
                        for (int j = t; j < pnpn; j += 256) {
                            int idx = (int)(__ldcg(&g_best[b*pnpn + j]) & 0xFFFull);
                            atomicAdd(&g_hits[idx], 1.f);
                        }
                    }
                    for (int j = t; j < 4*pnpn; j += 256) {
                        int c = j / pnpn, p = j - c*pnpn;
                        int idx = (int)(__ldcg(&g_best[b*pnpn + p]) & 0xFFFull);
                        hq[j] = emb[(size_t)idx*32 + cg*4 + c];
                    }
                    __syncthreads();
                    for (int j = t; j < 4*pn*32; j += 256) {
                        int c = j / (pn*32); int rem = j - c*(pn*32);
                        int h = rem >> 5; int X = rem & 31;
                        float acc = 0.f;
                        for (int wv = 0; wv < pn; wv++)
                            acc = fmaf(Ms[X*pn + wv], hq[c*pnpn + h*pn + wv], acc);
                        tmp[j] = acc;
                    }
                    __syncthreads();
                    for (int j = t; j < 4096; j += 256) {
                        int c = j >> 10, Y = (j >> 5) & 31, X = j & 31;
                        float acc = 0.f;
                        for (int hv = 0; hv < pn; hv++)
                            acc = fmaf(Ms[Y*pn + hv], tmp[(c*pn + hv)*32 + X], acc);
                        g_h32[((b*32 + cg*4 + c) << 10) + (Y << 5) + X] = acc;
                    }
                    __syncthreads();
                }
            }
            gridbar(NB);

            // ============ phi (ci in 2 halves) + f_rest update + reset g_best ============
            {
                const float* wgt  = pw + phiSel[si]*9216;
                const float* bias = pb + phiSel[si]*32;
                float* in_s = sm;                      // 16*1224
                ull*   w2   = (ull*)(sm + 19584);      // 1152
                float* b_s  = sm + 19584 + 2304;       // 4
                int Nn = 32 * pns[si+1]*pns[si+1];
                for (int i = blk*256 + t; i < Nn; i += NB*256) g_best[i] = ~0ull;
                for (int item = blk; item < 256; item += NB) {
                    __syncthreads();
                    int b = item >> 3, cog = item & 7;
                    for (int i = t; i < 1152; i += 256) {
                        float wv = wgt[cog*1152 + i]; w2[i] = pack2(wv, wv);
                    }
                    if (t < 4) b_s[t] = bias[cog*4 + t];
                    __syncthreads();
                    int y = t >> 3, x0 = (t & 7)*4;
                    ull accA[4], accB[4];
                    #pragma unroll
                    for (int k = 0; k < 4; k++) {
                        ull bb = pack2(b_s[k], b_s[k]); accA[k] = bb; accB[k] = bb;
                    }
                    const float* hb = g_h32 + (size_t)b*32768;
                    for (int h2 = 0; h2 < 2; h2++) {
                        for (int i = t; i < 16*PHI_CI; i += 256) {
                            int ci = i / PHI_CI; int rem = i - ci*PHI_CI;
                            int yy = rem / 36, xx = rem - yy*36;
                            float val = 0.f;
                            if (yy >= 1 && yy <= 32 && xx >= 1 && xx <= 32)
                                val = __ldcg(&hb[((h2*16 + ci) << 10) + ((yy-1) << 5) + (xx-1)]);
                            in_s[i] = val;
                        }
                        __syncthreads();
                        for (int ci = 0; ci < 16; ci++) {
                            ull pr[3][5];
                            #pragma unroll
                            for (int rr = 0; rr < 3; rr++) {
                                const float* row = in_s + ci*PHI_CI + (y+rr)*36 + x0;
                                float4 u03 = *(const float4*)row;
                                float2 u45 = *(const float2*)(row + 4);
                                pr[rr][0] = pack2(u03.x, u03.y);
                                pr[rr][1] = pack2(u03.y, u03.z);
                                pr[rr][2] = pack2(u03.z, u03.w);
                                pr[rr][3] = pack2(u03.w, u45.x);
                                pr[rr][4] = pack2(u45.x, u45.y);
                            }
                            #pragma unroll
                            for (int k = 0; k < 4; k++) {
                                const ull* wk = w2 + (size_t)(k*32 + h2*16 + ci)*9;
                                ull a = accA[k], c2 = accB[k];
                                #pragma unroll
                                for (int rr = 0; rr < 3; rr++) {
                                    ull w0 = wk[rr*3], w1 = wk[rr*3+1], wv2 = wk[rr*3+2];
                                    a  = fma2(pr[rr][0], w0, a);
                                    a  = fma2(pr[rr][1], w1, a);
                                    a  = fma2(pr[rr][2], wv2, a);
                                    c2 = fma2(pr[rr][2], w0, c2);
                                    c2 = fma2(pr[rr][3], w1, c2);
                                    c2 = fma2(pr[rr][4], wv2, c2);
                                }
                                accA[k] = a; accB[k] = c2;
                            }
                        }
                        __syncthreads();
                    }
                    #pragma unroll
                    for (int k = 0; k < 4; k++) {
                        float2 pa = unpack2(accA[k]);
                        float2 pbv = unpack2(accB[k]);
                        float conv[4] = {pa.x, pa.y, pbv.x, pbv.y};
                        int co = cog*4 + k;
                        #pragma unroll
                        for (int q = 0; q < 4; q++) {
                            int x = x0 + q;
                            float hval = __ldcg(&g_h32[((b*32 + co) << 10) + (y << 5) + x]);
                            float outv = 0.5f*hval + 0.5f*conv[q];
                            float* fp = &g_frest[((b*32 + co) << 10) + (y << 5) + x];
                            *fp = __ldcg(fp) - outv;
                        }
                    }
                }
            }
            gridbar(NB);
        } else {
            // hits for si=5
            for (int n = blk*256 + t; n < 32768; n += NB*256) {
                int idx = (int)(__ldcg(&g_best[n]) & 0xFFFull);
                atomicAdd(&g_hits[idx], 1.f);
            }
            gridbar(NB);
        }
    }

    // ================= final: loss + perplexity (block 0) =================
    if (blk == 0) {
        float* red = sm;
        float ssum = 0.f;
        for (int k = t; k < NB; k += 256) ssum += __ldcg(&g_part[k]);
        red[t] = ssum; __syncthreads();
        for (int o = 128; o > 0; o >>= 1) { if (t < o) red[t] += red[t+o]; __syncthreads(); }
        float S = red[0]; __syncthreads();
        float m = S / (float)NPIX;
        float h = 0.f;
        for (int k = 0; k < 16; k++) h += __ldcg(&g_hits[t + k*256]);
        red[t] = h; __syncthreads();
        for (int o = 128; o > 0; o >>= 1) { if (t < o) red[t] += red[t+o]; __syncthreads(); }
        float tot = red[0]; __syncthreads();
        float denom = fmaxf(tot, 1.f);
        float e = 0.f;
        for (int k = 0; k < 16; k++) {
            float p = __ldcg(&g_hits[t + k*256]) / denom;
            e += p * logf(p + 1e-10f);
        }
        red[t] = e; __syncthreads();
        for (int o = 128; o > 0; o >>= 1) { if (t < o) red[t] += red[t+o]; __syncthreads(); }
        if (t == 0) {
            float ent = red[0];
            float loss = 0.f;
            for (int si = 0; si < 6; si++) { loss = loss + 0.25f*m; loss = loss + m; }
            out[out_size - 2] = loss;
            out[out_size - 1] = expf(-ent);
        }
    }
}

// ---------------- launcher ----------------
extern "C" void kernel_launch(void* const* d_in, const int* in_sizes, int n_in,
                              void* d_out, int out_size) {
    const float* f   = (const float*)d_in[0];
    const float* emb = (const float*)d_in[1];
    const float* pw  = (const float*)d_in[2];
    const float* pb  = (const float*)d_in[3];
    float* out = (float*)d_out;

    const int SMEM = 90112;  // 88 KB: fits phi (87.6 KB) and argmin (78 KB)
    static int NB = 0;
    if (NB == 0) {
        int dev = 0; cudaGetDevice(&dev);
        int sms = 0;
        cudaDeviceGetAttribute(&sms, cudaDevAttrMultiProcessorCount, dev);
        if (sms <= 0) sms = 148;
        cudaFuncSetAttribute(mega, cudaFuncAttributeMaxDynamicSharedMemorySize, SMEM);
        int occ = 0;
        cudaOccupancyMaxActiveBlocksPerMultiprocessor(&occ, mega, 256, SMEM);
        if (occ < 1) occ = 1;
        if (occ > 2) occ = 2;
        NB = sms * occ;
        if (NB > 1024) NB = 1024;
    }
    mega<<<NB, 256, SMEM>>>((const float4*)f, emb, pw, pb, out, out_size, NB);
}

// round 7
// speedup vs baseline: 1.3140x; 1.3140x over previous
#include <cuda_runtime.h>
#include <math.h>
#include <float.h>

typedef unsigned long long ull;

#define NPIX (32*32*1024)
#define Vv 4096

// ---- static device scratch ----
__device__ float g_frest[NPIX];
__device__ float g_r[32*32*256];      // downsampled z, layout [(b*32+c)*pnpn + p]
__device__ float g_h32[NPIX];
__device__ float g_hits[Vv];
__device__ float g_esq[Vv];
__device__ float g_Mm[5][32][16];
__device__ float g_part[1024];
__device__ ull   g_best[32768];
__device__ unsigned g_ctr = 0;
__device__ unsigned g_gen = 0;

// ---- packed f32x2 helpers ----
__device__ __forceinline__ ull pack2(float lo, float hi) {
    ull d;
    asm("mov.b64 %0, {%1, %2};" : "=l"(d)
        : "r"(__float_as_uint(lo)), "r"(__float_as_uint(hi)));
    return d;
}
__device__ __forceinline__ float2 unpack2(ull v) {
    unsigned int lo, hi;
    asm("mov.b64 {%0, %1}, %2;" : "=r"(lo), "=r"(hi) : "l"(v));
    return make_float2(__uint_as_float(lo), __uint_as_float(hi));
}
__device__ __forceinline__ ull fma2(ull a, ull b, ull c) {
    ull d;
    asm("fma.rn.f32x2 %0, %1, %2, %3;" : "=l"(d) : "l"(a), "l"(b), "l"(c));
    return d;
}
__device__ __forceinline__ ull add2(ull a, ull b) {
    ull d;
    asm("add.rn.f32x2 %0, %1, %2;" : "=l"(d) : "l"(a), "l"(b));
    return d;
}

// ---- grid-wide barrier (all blocks resident; generation counting) ----
__device__ __forceinline__ void gridbar(int NB) {
    __syncthreads();
    if (threadIdx.x == 0) {
        __threadfence();
        unsigned gen = *((volatile unsigned*)&g_gen);
        if (atomicAdd(&g_ctr, 1u) == (unsigned)(NB - 1)) {
            *((volatile unsigned*)&g_ctr) = 0u;
            __threadfence();
            atomicAdd(&g_gen, 1u);
        } else {
            while (*((volatile unsigned*)&g_gen) == gen) __nanosleep(32);
        }
        __threadfence();
    }
    __syncthreads();
}

__device__ __forceinline__ ull enc_key(float d, int idx) {
    unsigned u = __float_as_uint(d);
    u = (u & 0x80000000u) ? ~u : (u | 0x80000000u);
    return ((ull)u << 12) | (unsigned)idx;
}

#define PHI_CI 1224   // 34*36 padded channel plane

extern "C" __global__ void __launch_bounds__(256, 2)
mega(const float4* __restrict__ f, const float* __restrict__ emb,
     const float* __restrict__ pw, const float* __restrict__ pb,
     float* __restrict__ out, int out_size, int NB)
{
    extern __shared__ float sm[];
    int t = threadIdx.x, blk = blockIdx.x;

    // ================= phase 0: prep =================
    {
        float s = 0.f;
        float4* out4 = (float4*)out;
        for (int i = blk*256 + t; i < NPIX/4; i += NB*256) {
            float4 v = f[i];
            ((float4*)g_frest)[i] = v;
            s = fmaf(v.x, v.x, fmaf(v.y, v.y, fmaf(v.z, v.z, fmaf(v.w, v.w, s))));
            out4[i] = make_float4(0.f, 0.f, 0.f, 0.f);
        }
        sm[t] = s; __syncthreads();
        for (int o = 128; o > 0; o >>= 1) { if (t < o) sm[t] += sm[t+o]; __syncthreads(); }
        if (t == 0) g_part[blk] = sm[0];

        // plane means for si=0 (pn=1): one warp per (b,c) plane
        {
            int gw = blk*8 + (t >> 5), l = t & 31;
            if (gw < 1024) {
                const float4* pf = f + gw*256;
                float acc = 0.f;
                for (int i = l; i < 256; i += 32) {
                    float4 v = pf[i]; acc += (v.x + v.y) + (v.z + v.w);
                }
                #pragma unroll
                for (int off = 16; off; off >>= 1) acc += __shfl_down_sync(~0u, acc, off);
                if (l == 0) g_r[gw] = acc * (1.f/1024.f);
            }
        }

        for (int v = blk*256 + t; v < Vv; v += NB*256) {
            g_hits[v] = 0.f;
            const float* e = emb + v*32;
            float acc = 0.f;
            #pragma unroll
            for (int c = 0; c < 32; c++) acc += e[c]*e[c];
            g_esq[v] = acc;
        }
        for (int i = blk*256 + t; i < 160; i += NB*256) {
            int si = i >> 5, r = i & 31;
            const int pns5[5] = {1,2,4,8,16};
            int pn = pns5[si];
            for (int j = 0; j < 16; j++) g_Mm[si][r][j] = 0.f;
            double scale = (double)pn / 32.0;
            double x = (r + 0.5)*scale - 0.5;
            double x0 = floor(x);
            double tt = x - x0;
            int ix0 = (int)x0;
            const double a = -0.75;
            for (int j = -1; j <= 2; j++) {
                double d = fabs(tt - (double)j);
                double w;
                if (d < 1.0)      w = (a+2.0)*d*d*d - (a+3.0)*d*d + 1.0;
                else if (d < 2.0) w = a*d*d*d - 5.0*a*d*d + 8.0*a*d - 4.0*a;
                else              w = 0.0;
                int col = ix0 + j;
                col = col < 0 ? 0 : (col > pn-1 ? pn-1 : col);
                g_Mm[si][r][col] = (float)((double)g_Mm[si][r][col] + w);
            }
        }
        for (int i = blk*256 + t; i < 32; i += NB*256) g_best[i] = ~0ull;
    }
    gridbar(NB);

    const int pns[6]    = {1,2,4,8,16,32};
    const int VSs[6]    = {128,64,16,8,2,4};
    const int phiSel[6] = {0,0,1,2,3,3};

    for (int si = 0; si < 6; si++) {
        int pn = pns[si], pnpn = pn*pn, N = 32*pnpn, VS = VSs[si];
        int chunk = 4096 / VS;
        int TC = chunk < 512 ? chunk : 512;

        float4* es4   = (float4*)sm;
        float*  esq_s = sm + (size_t)TC*32;
        ull*    z2t   = (ull*)(sm + (size_t)TC*33);
        float*  sdA   = (float*)(z2t + 1024);
        float*  sdB   = sdA + 256;
        int*    svA   = (int*)(sdB + 256);
        int*    svB   = svA + 256;

        // ============ argmin ============
        if (pn == 1) {
            int items = VS;
            for (int item = blk; item < items; item += NB) {
                __syncthreads();
                int vc = item;
                {   // z from g_r: thread -> row t>>3, 4 channels
                    int r = t >> 3, cq = (t & 7)*4;
                    float zc[4];
                    #pragma unroll
                    for (int q = 0; q < 4; q++) zc[q] = g_r[r*32 + cq + q];
                    int i0 = cq >> 1;
                    z2t[i0*32 + r]     = pack2(zc[0], zc[1]);
                    z2t[(i0+1)*32 + r] = pack2(zc[2], zc[3]);
                }
                __syncthreads();
                int w = t >> 5, l = t & 31;
                ull zp[16];
                #pragma unroll
                for (int i = 0; i < 16; i++) zp[i] = z2t[i*32 + l];
                float best = FLT_MAX; int bv = 0;
                int v0 = vc*chunk;
                for (int t0 = v0; t0 < v0 + chunk; t0 += TC) {
                    __syncthreads();
                    const float4* eg = (const float4*)(emb + (size_t)t0*32);
                    for (int i = t; i < TC*8; i += 256) es4[i] = eg[i];
                    for (int i = t; i < TC;   i += 256) esq_s[i] = g_esq[t0 + i];
                    __syncthreads();
                    for (int v = w; v < TC; v += 8) {
                        const ulonglong2* evp = (const ulonglong2*)(es4 + v*8);
                        ull a0 = 0ull, a1 = 0ull;
                        #pragma unroll
                        for (int i = 0; i < 8; i++) {
                            ulonglong2 q = evp[i];
                            a0 = fma2(zp[2*i],   q.x, a0);
                            a1 = fma2(zp[2*i+1], q.y, a1);
                        }
                        float2 pq = unpack2(add2(a0, a1));
                        float dist = fmaf(-2.f, pq.x + pq.y, esq_s[v]);
                        if (dist < best) { best = dist; bv = t0 + v; }
                    }
                }
                sdA[t] = best; svA[t] = bv;
                __syncthreads();
                if (w == 0) {
                    float bb = sdA[l]; int vv = svA[l];
                    #pragma unroll
                    for (int k = 1; k < 8; k++) {
                        float d2 = sdA[k*32 + l]; int v2 = svA[k*32 + l];
                        if (d2 < bb || (d2 == bb && v2 < vv)) { bb = d2; vv = v2; }
                    }
                    atomicMin(&g_best[l], enc_key(bb, vv));
                }
            }
        } else {
            int G = N / 64;
            int items = G * VS;
            for (int item = blk; item < items; item += NB) {
                __syncthreads();
                int g = item % G, vc = item / G;
                {   // z: thread -> row t>>2 (0..63), 8 channels, from g_r (or frest at pn=32)
                    int r = t >> 2, cq = (t & 3)*8;
                    int n = g*64 + r;
                    int b = n / pnpn, p = n - b*pnpn;
                    float zc[8];
                    if (pn == 32) {
                        #pragma unroll
                        for (int q = 0; q < 8; q++)
                            zc[q] = g_frest[((b*32 + cq + q) << 10) + p];
                    } else {
                        #pragma unroll
                        for (int q = 0; q < 8; q++)
                            zc[q] = g_r[(b*32 + cq + q)*pnpn + p];
                    }
                    int i0 = cq >> 1;
                    #pragma unroll
                    for (int j = 0; j < 4; j++)
                        z2t[(i0+j)*64 + r] = pack2(zc[2*j], zc[2*j+1]);
                }
                __syncthreads();
                int w = t >> 5, l = t & 31;
                ull zpA[16], zpB[16];
                #pragma unroll
                for (int i = 0; i < 16; i++) {
                    zpA[i] = z2t[i*64 + l];
                    zpB[i] = z2t[i*64 + 32 + l];
                }
                float bestA = FLT_MAX, bestB = FLT_MAX; int bvA = 0, bvB = 0;
                int v0 = vc*chunk;
                for (int t0 = v0; t0 < v0 + chunk; t0 += TC) {
                    __syncthreads();
                    const float4* eg = (const float4*)(emb + (size_t)t0*32);
                    for (int i = t; i < TC*8; i += 256) es4[i] = eg[i];
                    for (int i = t; i < TC;   i += 256) esq_s[i] = g_esq[t0 + i];
                    __syncthreads();
                    for (int v = w; v < TC; v += 8) {
                        const ulonglong2* evp = (const ulonglong2*)(es4 + v*8);
                        ull a0 = 0ull, a1 = 0ull, b0 = 0ull, b1 = 0ull;
                        #pragma unroll
                        for (int i = 0; i < 8; i++) {
                            ulonglong2 q = evp[i];
                            a0 = fma2(zpA[2*i],   q.x, a0);
                            a1 = fma2(zpA[2*i+1], q.y, a1);
                            b0 = fma2(zpB[2*i],   q.x, b0);
                            b1 = fma2(zpB[2*i+1], q.y, b1);
                        }
                        float2 pa = unpack2(add2(a0, a1));
                        float dA = fmaf(-2.f, pa.x + pa.y, esq_s[v]);
                        float2 pbv = unpack2(add2(b0, b1));
                        float dB = fmaf(-2.f, pbv.x + pbv.y, esq_s[v]);
                        if (dA < bestA) { bestA = dA; bvA = t0 + v; }
                        if (dB < bestB) { bestB = dB; bvB = t0 + v; }
                    }
                }
                sdA[t] = bestA; svA[t] = bvA; sdB[t] = bestB; svB[t] = bvB;
                __syncthreads();
                int w2i = t >> 5, l2 = t & 31;
                if (w2i == 0) {
                    float bb = sdA[l2]; int vv = svA[l2];
                    #pragma unroll
                    for (int k = 1; k < 8; k++) {
                        float d2 = sdA[k*32 + l2]; int v2 = svA[k*32 + l2];
                        if (d2 < bb || (d2 == bb && v2 < vv)) { bb = d2; vv = v2; }
                    }
                    atomicMin(&g_best[g*64 + l2], enc_key(bb, vv));
                } else if (w2i == 1) {
                    float bb = sdB[l2]; int vv = svB[l2];
                    #pragma unroll
                    for (int k = 1; k < 8; k++) {
                        float d2 = sdB[k*32 + l2]; int v2 = svB[k*32 + l2];
                        if (d2 < bb || (d2 == bb && v2 < vv)) { bb = d2; vv = v2; }
                    }
                    atomicMin(&g_best[g*64 + 32 + l2], enc_key(bb, vv));
                }
            }
        }
        gridbar(NB);

        if (si < 5) {
            // ============ ups (+hits) ============
            {
                float* hq  = sm;
                float* tmp = hq + 4*pnpn;
                float* Ms  = tmp + 4*pn*32;
                for (int item = blk; item < 256; item += NB) {
                    __syncthreads();
                    int b = item >> 3, cg = item & 7;
                    for (int i = t; i < 32*pn; i += 256) Ms[i] = g_Mm[si][i/pn][i%pn];
                    if (cg == 0) {
                        for (int j = t; j < pnpn; j += 256) {
                            int idx = (int)(g_best[b*pnpn + j] & 0xFFFull);
                            atomicAdd(&g_hits[idx], 1.f);
                        }
                    }
                    for (int j = t; j < 4*pnpn; j += 256) {
                        int c = j / pnpn, p = j - c*pnpn;
                        int idx = (int)(g_best[b*pnpn + p] & 0xFFFull);
                        hq[j] = emb[(size_t)idx*32 + cg*4 + c];
                    }
                    __syncthreads();
                    for (int j = t; j < 4*pn*32; j += 256) {
                        int c = j / (pn*32); int rem = j - c*(pn*32);
                        int h = rem >> 5; int X = rem & 31;
                        float acc = 0.f;
                        for (int wv = 0; wv < pn; wv++)
                            acc = fmaf(Ms[X*pn + wv], hq[c*pnpn + h*pn + wv], acc);
                        tmp[j] = acc;
                    }
                    __syncthreads();
                    for (int j = t; j < 4096; j += 256) {
                        int c = j >> 10, Y = (j >> 5) & 31, X = j & 31;
                        float acc = 0.f;
                        for (int hv = 0; hv < pn; hv++)
                            acc = fmaf(Ms[Y*pn + hv], tmp[(c*pn + hv)*32 + X], acc);
                        g_h32[((b*32 + cg*4 + c) << 10) + (Y << 5) + X] = acc;
                    }
                    __syncthreads();
                }
            }
            gridbar(NB);

            // ==== phi + f_rest update + pooled g_r for next scale + g_best reset ====
            {
                const float* wgt  = pw + phiSel[si]*9216;
                const float* bias = pb + phiSel[si]*32;
                float* in_s = sm;                      // 16*1224 (reused as pool later)
                ull*   w2   = (ull*)(sm + 19584);      // 1152
                float* b_s  = sm + 19584 + 2304;       // 4
                float* pool = sm;                      // 4*1024 after conv done
                int pn2 = pns[si+1], pn22 = pn2*pn2;
                int s2 = 32 / pn2, s22 = s2*s2;
                float invp = 1.f / (float)s22;
                int Nn = 32 * pn22;
                for (int i = blk*256 + t; i < Nn; i += NB*256) g_best[i] = ~0ull;
                for (int item = blk; item < 256; item += NB) {
                    __syncthreads();
                    int b = item >> 3, cog = item & 7;
                    for (int i = t; i < 1152; i += 256) {
                        float wv = wgt[cog*1152 + i]; w2[i] = pack2(wv, wv);
                    }
                    if (t < 4) b_s[t] = bias[cog*4 + t];
                    __syncthreads();
                    int y = t >> 3, x0 = (t & 7)*4;
                    ull accA[4], accB[4];
                    #pragma unroll
                    for (int k = 0; k < 4; k++) {
                        ull bb = pack2(b_s[k], b_s[k]); accA[k] = bb; accB[k] = bb;
                    }
                    const float* hb = g_h32 + (size_t)b*32768;
                    for (int h2 = 0; h2 < 2; h2++) {
                        for (int i = t; i < 16*PHI_CI; i += 256) {
                            int ci = i / PHI_CI; int rem = i - ci*PHI_CI;
                            int yy = rem / 36, xx = rem - yy*36;
                            float val = 0.f;
                            if (yy >= 1 && yy <= 32 && xx >= 1 && xx <= 32)
                                val = hb[((h2*16 + ci) << 10) + ((yy-1) << 5) + (xx-1)];
                            in_s[i] = val;
                        }
                        __syncthreads();
                        for (int ci = 0; ci < 16; ci++) {
                            ull pr[3][5];
                            #pragma unroll
                            for (int rr = 0; rr < 3; rr++) {
                                const float* row = in_s + ci*PHI_CI + (y+rr)*36 + x0;
                                float4 u03 = *(const float4*)row;
                                float2 u45 = *(const float2*)(row + 4);
                                pr[rr][0] = pack2(u03.x, u03.y);
                                pr[rr][1] = pack2(u03.y, u03.z);
                                pr[rr][2] = pack2(u03.z, u03.w);
                                pr[rr][3] = pack2(u03.w, u45.x);
                                pr[rr][4] = pack2(u45.x, u45.y);
                            }
                            #pragma unroll
                            for (int k = 0; k < 4; k++) {
                                const ull* wk = w2 + (size_t)(k*32 + h2*16 + ci)*9;
                                ull a = accA[k], c2 = accB[k];
                                #pragma unroll
                                for (int rr = 0; rr < 3; rr++) {
                                    ull w0 = wk[rr*3], w1 = wk[rr*3+1], wv2 = wk[rr*3+2];
                                    a  = fma2(pr[rr][0], w0, a);
                                    a  = fma2(pr[rr][1], w1, a);
                                    a  = fma2(pr[rr][2], wv2, a);
                                    c2 = fma2(pr[rr][2], w0, c2);
                                    c2 = fma2(pr[rr][3], w1, c2);
                                    c2 = fma2(pr[rr][4], wv2, c2);
                                }
                                accA[k] = a; accB[k] = c2;
                            }
                        }
                        __syncthreads();
                    }
                    // writeback + stage updated tile for pooling
                    #pragma unroll
                    for (int k = 0; k < 4; k++) {
                        float2 pa = unpack2(accA[k]);
                        float2 pbv = unpack2(accB[k]);
                        float conv[4] = {pa.x, pa.y, pbv.x, pbv.y};
                        int co = cog*4 + k;
                        #pragma unroll
                        for (int q = 0; q < 4; q++) {
                            int x = x0 + q;
                            int gi = ((b*32 + co) << 10) + (y << 5) + x;
                            float hval = g_h32[gi];
                            float newv = g_frest[gi] - (0.5f*hval + 0.5f*conv[q]);
                            g_frest[gi] = newv;
                            pool[k*1024 + (y << 5) + x] = newv;
                        }
                    }
                    __syncthreads();
                    // pooled downsample for next scale (skip if next is pn=32)
                    if (pn2 < 32) {
                        int w = t >> 5, l = t & 31;
                        for (int o = w; o < 4*pn22; o += 8) {
                            int k = o / pn22, p = o - k*pn22;
                            int ph = p / pn2, pw2 = p - ph*pn2;
                            float acc = 0.f;
                            for (int e = l; e < s22; e += 32) {
                                int dy = e / s2, dx = e - dy*s2;
                                acc += pool[k*1024 + ((ph*s2 + dy) << 5) + (pw2*s2 + dx)];
                            }
                            #pragma unroll
                            for (int off = 16; off; off >>= 1)
                                acc += __shfl_down_sync(~0u, acc, off);
                            if (l == 0)
                                g_r[(b*32 + cog*4 + k)*pn22 + p] = acc * invp;
                        }
                    }
                    __syncthreads();
                }
            }
            gridbar(NB);
        } else {
            // hits for si=5
            for (int n = blk*256 + t; n < 32768; n += NB*256) {
                int idx = (int)(g_best[n] & 0xFFFull);
                atomicAdd(&g_hits[idx], 1.f);
            }
            gridbar(NB);
        }
    }

    // ================= final: loss + perplexity (block 0) =================
    if (blk == 0) {
        float* red = sm;
        float ssum = 0.f;
        for (int k = t; k < NB; k += 256) ssum += g_part[k];
        red[t] = ssum; __syncthreads();
        for (int o = 128; o > 0; o >>= 1) { if (t < o) red[t] += red[t+o]; __syncthreads(); }
        float S = red[0]; __syncthreads();
        float m = S / (float)NPIX;
        float h = 0.f;
        for (int k = 0; k < 16; k++) h += g_hits[t + k*256];
        red[t] = h; __syncthreads();
        for (int o = 128; o > 0; o >>= 1) { if (t < o) red[t] += red[t+o]; __syncthreads(); }
        float tot = red[0]; __syncthreads();
        float denom = fmaxf(tot, 1.f);
        float e = 0.f;
        for (int k = 0; k < 16; k++) {
            float p = g_hits[t + k*256] / denom;
            e += p * logf(p + 1e-10f);
        }
        red[t] = e; __syncthreads();
        for (int o = 128; o > 0; o >>= 1) { if (t < o) red[t] += red[t+o]; __syncthreads(); }
        if (t == 0) {
            float ent = red[0];
            float loss = 0.f;
            for (int si = 0; si < 6; si++) { loss = loss + 0.25f*m; loss = loss + m; }
            out[out_size - 2] = loss;
            out[out_size - 1] = expf(-ent);
        }
    }
}

// ---------------- launcher ----------------
extern "C" void kernel_launch(void* const* d_in, const int* in_sizes, int n_in,
                              void* d_out, int out_size) {
    const float* f   = (const float*)d_in[0];
    const float* emb = (const float*)d_in[1];
    const float* pw  = (const float*)d_in[2];
    const float* pb  = (const float*)d_in[3];
    float* out = (float*)d_out;

    const int SMEM = 90112;  // 88 KB
    static int NB = 0;
    if (NB == 0) {
        int dev = 0; cudaGetDevice(&dev);
        int sms = 0;
        cudaDeviceGetAttribute(&sms, cudaDevAttrMultiProcessorCount, dev);
        if (sms <= 0) sms = 148;
        cudaFuncSetAttribute(mega, cudaFuncAttributeMaxDynamicSharedMemorySize, SMEM);
        int occ = 0;
        cudaOccupancyMaxActiveBlocksPerMultiprocessor(&occ, mega, 256, SMEM);
        if (occ < 1) occ = 1;
        if (occ > 2) occ = 2;
        NB = sms * occ;
        if (NB > 1024) NB = 1024;
    }
    mega<<<NB, 256, SMEM>>>((const float4*)f, emb, pw, pb, out, out_size, NB);
}

// round 8
// speedup vs baseline: 2.2155x; 1.6860x over previous
#include <cuda_runtime.h>
#include <math.h>
#include <float.h>

typedef unsigned long long ull;

#define NPIX (32*32*1024)
#define Vv 4096

// ---- static device scratch ----
__device__ float g_frest[NPIX];
__device__ float g_r[32*32*256];      // downsampled z, layout [(b*32+c)*pnpn + p]
__device__ float g_h32[NPIX];
__device__ float g_hits[Vv];
__device__ float g_esq[Vv];
__device__ float g_Mm[5][32][16];
__device__ float g_part[512];
__device__ ull   g_best[32768];

// ---- packed f32x2 helpers (FFMA2) ----
__device__ __forceinline__ ull pack2(float lo, float hi) {
    ull d;
    asm("mov.b64 %0, {%1, %2};" : "=l"(d)
        : "r"(__float_as_uint(lo)), "r"(__float_as_uint(hi)));
    return d;
}
__device__ __forceinline__ float2 unpack2(ull v) {
    unsigned int lo, hi;
    asm("mov.b64 {%0, %1}, %2;" : "=r"(lo), "=r"(hi) : "l"(v));
    return make_float2(__uint_as_float(lo), __uint_as_float(hi));
}
__device__ __forceinline__ ull fma2(ull a, ull b, ull c) {
    ull d;
    asm("fma.rn.f32x2 %0, %1, %2, %3;" : "=l"(d) : "l"(a), "l"(b), "l"(c));
    return d;
}
__device__ __forceinline__ ull add2(ull a, ull b) {
    ull d;
    asm("add.rn.f32x2 %0, %1, %2;" : "=l"(d) : "l"(a), "l"(b));
    return d;
}

__device__ __forceinline__ ull enc_key(float d, int idx) {
    unsigned u = __float_as_uint(d);
    u = (u & 0x80000000u) ? ~u : (u | 0x80000000u);
    return ((ull)u << 12) | (unsigned)idx;
}

// ================ prep: copy, zero out, f^2, plane means, esq, M, g_best init ================
__global__ void __launch_bounds__(256) k_prep(const float4* __restrict__ f,
                                              float4* __restrict__ out4,
                                              const float* __restrict__ emb) {
    __shared__ float red[256];
    int t = threadIdx.x, blk = blockIdx.x;
    float s = 0.f;
    for (int i = blk*256 + t; i < NPIX/4; i += gridDim.x*256) {
        float4 v = f[i];
        ((float4*)g_frest)[i] = v;
        s = fmaf(v.x, v.x, fmaf(v.y, v.y, fmaf(v.z, v.z, fmaf(v.w, v.w, s))));
        out4[i] = make_float4(0.f, 0.f, 0.f, 0.f);
    }
    red[t] = s; __syncthreads();
    for (int o = 128; o > 0; o >>= 1) { if (t < o) red[t] += red[t+o]; __syncthreads(); }
    if (t == 0) g_part[blk] = red[0];

    // plane means for si=0 (pn=1): one warp per (b,c) plane
    {
        int gw = blk*8 + (t >> 5), l = t & 31;
        if (gw < 1024) {
            const float4* pf = f + gw*256;
            float acc = 0.f;
            for (int i = l; i < 256; i += 32) {
                float4 v = pf[i]; acc += (v.x + v.y) + (v.z + v.w);
            }
            #pragma unroll
            for (int off = 16; off; off >>= 1) acc += __shfl_down_sync(~0u, acc, off);
            if (l == 0) g_r[gw] = acc * (1.f/1024.f);
        }
    }
    for (int v = blk*256 + t; v < Vv; v += gridDim.x*256) {
        g_hits[v] = 0.f;
        const float* e = emb + v*32;
        float acc = 0.f;
        #pragma unroll
        for (int c = 0; c < 32; c++) acc += e[c]*e[c];
        g_esq[v] = acc;
    }
    if (blk == 0) {
        if (t < 160) {
            int si = t >> 5, r = t & 31;
            const int pns5[5] = {1,2,4,8,16};
            int pn = pns5[si];
            for (int j = 0; j < 16; j++) g_Mm[si][r][j] = 0.f;
            double scale = (double)pn / 32.0;
            double x = (r + 0.5)*scale - 0.5;
            double x0 = floor(x);
            double tt = x - x0;
            int ix0 = (int)x0;
            const double a = -0.75;
            for (int j = -1; j <= 2; j++) {
                double d = fabs(tt - (double)j);
                double w;
                if (d < 1.0)      w = (a+2.0)*d*d*d - (a+3.0)*d*d + 1.0;
                else if (d < 2.0) w = a*d*d*d - 5.0*a*d*d + 8.0*a*d - 4.0*a;
                else              w = 0.0;
                int col = ix0 + j;
                col = col < 0 ? 0 : (col > pn-1 ? pn-1 : col);
                g_Mm[si][r][col] = (float)((double)g_Mm[si][r][col] + w);
            }
        }
        if (t < 32) g_best[t] = ~0ull;   // for si=0
    }
}

// ================ argmin: grid-strided items, atomicMin(u64) reduce ================
// mode 0: pn==1 (32 rows, z from g_r)
// mode 1: 64-row groups, z from g_r
// mode 2: 64-row groups, z from g_frest (pn==32)
__global__ void __launch_bounds__(256, 2) k_argmin(const float* __restrict__ emb,
                                                   int pnpn, int G, int chunk,
                                                   int TC, int items, int mode) {
    extern __shared__ float sm[];
    float4* es4   = (float4*)sm;
    float*  esq_s = sm + (size_t)TC*32;
    ull*    z2t   = (ull*)(sm + (size_t)TC*33);
    float*  sdA   = (float*)(z2t + 1024);
    float*  sdB   = sdA + 256;
    int*    svA   = (int*)(sdB + 256);
    int*    svB   = svA + 256;
    int t = threadIdx.x;

    if (mode == 0) {
        for (int item = blockIdx.x; item < items; item += gridDim.x) {
            __syncthreads();
            {   // z: thread -> row t>>3, 4 channels
                int r = t >> 3, cq = (t & 7)*4;
                float zc[4];
                #pragma unroll
                for (int q = 0; q < 4; q++) zc[q] = g_r[r*32 + cq + q];
                int i0 = cq >> 1;
                z2t[i0*32 + r]     = pack2(zc[0], zc[1]);
                z2t[(i0+1)*32 + r] = pack2(zc[2], zc[3]);
            }
            __syncthreads();
            int w = t >> 5, l = t & 31;
            ull zp[16];
            #pragma unroll
            for (int i = 0; i < 16; i++) zp[i] = z2t[i*32 + l];
            float best = FLT_MAX; int bv = 0;
            int v0 = item*chunk;
            for (int t0 = v0; t0 < v0 + chunk; t0 += TC) {
                __syncthreads();
                const float4* eg = (const float4*)(emb + (size_t)t0*32);
                for (int i = t; i < TC*8; i += 256) es4[i] = eg[i];
                for (int i = t; i < TC;   i += 256) esq_s[i] = g_esq[t0 + i];
                __syncthreads();
                for (int v = w; v < TC; v += 8) {
                    const ulonglong2* evp = (const ulonglong2*)(es4 + v*8);
                    ull a0 = 0ull, a1 = 0ull;
                    #pragma unroll
                    for (int i = 0; i < 8; i++) {
                        ulonglong2 q = evp[i];
                        a0 = fma2(zp[2*i],   q.x, a0);
                        a1 = fma2(zp[2*i+1], q.y, a1);
                    }
                    float2 pq = unpack2(add2(a0, a1));
                    float dist = fmaf(-2.f, pq.x + pq.y, esq_s[v]);
                    if (dist < best) { best = dist; bv = t0 + v; }
                }
            }
            sdA[t] = best; svA[t] = bv;
            __syncthreads();
            if (w == 0) {
                float bb = sdA[l]; int vv = svA[l];
                #pragma unroll
                for (int k = 1; k < 8; k++) {
                    float d2 = sdA[k*32 + l]; int v2 = svA[k*32 + l];
                    if (d2 < bb || (d2 == bb && v2 < vv)) { bb = d2; vv = v2; }
                }
                atomicMin(&g_best[l], enc_key(bb, vv));
            }
        }
    } else {
        for (int item = blockIdx.x; item < items; item += gridDim.x) {
            __syncthreads();
            int g = item % G, vc = item / G;
            {   // z: thread -> row t>>2 (0..63), 8 channels
                int r = t >> 2, cq = (t & 3)*8;
                int n = g*64 + r;
                int b = n / pnpn, p = n - b*pnpn;
                float zc[8];
                if (mode == 2) {
                    #pragma unroll
                    for (int q = 0; q < 8; q++)
                        zc[q] = g_frest[((b*32 + cq + q) << 10) + p];
                } else {
                    #pragma unroll
                    for (int q = 0; q < 8; q++)
                        zc[q] = g_r[(b*32 + cq + q)*pnpn + p];
                }
                int i0 = cq >> 1;
                #pragma unroll
                for (int j = 0; j < 4; j++)
                    z2t[(i0+j)*64 + r] = pack2(zc[2*j], zc[2*j+1]);
            }
            __syncthreads();
            int w = t >> 5, l = t & 31;
            ull zpA[16], zpB[16];
            #pragma unroll
            for (int i = 0; i < 16; i++) {
                zpA[i] = z2t[i*64 + l];
                zpB[i] = z2t[i*64 + 32 + l];
            }
            float bestA = FLT_MAX, bestB = FLT_MAX; int bvA = 0, bvB = 0;
            int v0 = vc*chunk;
            for (int t0 = v0; t0 < v0 + chunk; t0 += TC) {
                __syncthreads();
                const float4* eg = (const float4*)(emb + (size_t)t0*32);
                for (int i = t; i < TC*8; i += 256) es4[i] = eg[i];
                for (int i = t; i < TC;   i += 256) esq_s[i] = g_esq[t0 + i];
                __syncthreads();
                for (int v = w; v < TC; v += 8) {
                    const ulonglong2* evp = (const ulonglong2*)(es4 + v*8);
                    ull a0 = 0ull, a1 = 0ull, b0 = 0ull, b1 = 0ull;
                    #pragma unroll
                    for (int i = 0; i < 8; i++) {
                        ulonglong2 q = evp[i];
                        a0 = fma2(zpA[2*i],   q.x, a0);
                        a1 = fma2(zpA[2*i+1], q.y, a1);
                        b0 = fma2(zpB[2*i],   q.x, b0);
                        b1 = fma2(zpB[2*i+1], q.y, b1);
                    }
                    float2 pa = unpack2(add2(a0, a1));
                    float dA = fmaf(-2.f, pa.x + pa.y, esq_s[v]);
                    float2 pbv = unpack2(add2(b0, b1));
                    float dB = fmaf(-2.f, pbv.x + pbv.y, esq_s[v]);
                    if (dA < bestA) { bestA = dA; bvA = t0 + v; }
                    if (dB < bestB) { bestB = dB; bvB = t0 + v; }
                }
            }
            sdA[t] = bestA; svA[t] = bvA; sdB[t] = bestB; svB[t] = bvB;
            __syncthreads();
            int w2i = t >> 5, l2 = t & 31;
            if (w2i == 0) {
                float bb = sdA[l2]; int vv = svA[l2];
                #pragma unroll
                for (int k = 1; k < 8; k++) {
                    float d2 = sdA[k*32 + l2]; int v2 = svA[k*32 + l2];
                    if (d2 < bb || (d2 == bb && v2 < vv)) { bb = d2; vv = v2; }
                }
                atomicMin(&g_best[g*64 + l2], enc_key(bb, vv));
            } else if (w2i == 1) {
                float bb = sdB[l2]; int vv = svB[l2];
                #pragma unroll
                for (int k = 1; k < 8; k++) {
                    float d2 = sdB[k*32 + l2]; int v2 = svB[k*32 + l2];
                    if (d2 < bb || (d2 == bb && v2 < vv)) { bb = d2; vv = v2; }
                }
                atomicMin(&g_best[g*64 + 32 + l2], enc_key(bb, vv));
            }
        }
    }
}

// ================ ups: gather + separable bicubic (grid 256 = B x 8 ch-groups) + hits ================
__global__ void __launch_bounds__(256) k_ups(const float* __restrict__ emb, int pn, int sidx) {
    extern __shared__ float sm[];
    int pnpn = pn * pn;
    float* hq  = sm;
    float* tmp = hq + 4*pnpn;
    float* Ms  = tmp + 4*pn*32;
    int b = blockIdx.x >> 3, cg = blockIdx.x & 7, t = threadIdx.x;
    for (int i = t; i < 32*pn; i += 256) Ms[i] = g_Mm[sidx][i/pn][i%pn];
    if (cg == 0) {
        for (int j = t; j < pnpn; j += 256) {
            int idx = (int)(g_best[b*pnpn + j] & 0xFFFull);
            atomicAdd(&g_hits[idx], 1.f);
        }
    }
    for (int j = t; j < 4*pnpn; j += 256) {
        int c = j / pnpn, p = j - c*pnpn;
        int idx = (int)(g_best[b*pnpn + p] & 0xFFFull);
        hq[j] = emb[(size_t)idx*32 + cg*4 + c];
    }
    __syncthreads();
    for (int j = t; j < 4*pn*32; j += 256) {
        int c = j / (pn*32); int rem = j - c*(pn*32);
        int h = rem >> 5; int X = rem & 31;
        float acc = 0.f;
        for (int wv = 0; wv < pn; wv++)
            acc = fmaf(Ms[X*pn + wv], hq[c*pnpn + h*pn + wv], acc);
        tmp[j] = acc;
    }
    __syncthreads();
    for (int j = t; j < 4096; j += 256) {
        int c = j >> 10, Y = (j >> 5) & 31, X = j & 31;
        float acc = 0.f;
        for (int hv = 0; hv < pn; hv++)
            acc = fmaf(Ms[Y*pn + hv], tmp[(c*pn + hv)*32 + X], acc);
        g_h32[((b*32 + cg*4 + c) << 10) + (Y << 5) + X] = acc;
    }
}

// ================ phi: conv residual + f_rest update + pool next g_r + reset g_best ================
#define PHI_CI 1224   // 34*36
__global__ void __launch_bounds__(256, 2) k_phi(const float* __restrict__ wgt,
                                                const float* __restrict__ bias,
                                                int pn2) {
    extern __shared__ float sm[];
    float* in_s = sm;                      // 16*1224
    ull*   w2   = (ull*)(sm + 19584);      // 1152
    float* b_s  = sm + 19584 + 2304;       // 4
    float* pool = sm;                      // 4*1024 (reuses in_s)
    int b = blockIdx.x >> 3, cog = blockIdx.x & 7, t = threadIdx.x;
    int pn22 = pn2*pn2;
    int s2 = 32 / pn2, s22 = s2*s2;
    float invp = 1.f / (float)s22;
    // reset g_best for next scale
    for (int i = blockIdx.x*256 + t; i < 32*pn22; i += gridDim.x*256) g_best[i] = ~0ull;

    for (int i = t; i < 1152; i += 256) {
        float wv = wgt[cog*1152 + i]; w2[i] = pack2(wv, wv);
    }
    if (t < 4) b_s[t] = bias[cog*4 + t];
    __syncthreads();
    int y = t >> 3, x0 = (t & 7)*4;
    ull accA[4], accB[4];
    #pragma unroll
    for (int k = 0; k < 4; k++) {
        ull bb = pack2(b_s[k], b_s[k]); accA[k] = bb; accB[k] = bb;
    }
    const float* hb = g_h32 + (size_t)b*32768;
    for (int h2 = 0; h2 < 2; h2++) {
        for (int i = t; i < 16*PHI_CI; i += 256) {
            int ci = i / PHI_CI; int rem = i - ci*PHI_CI;
            int yy = rem / 36, xx = rem - yy*36;
            float val = 0.f;
            if (yy >= 1 && yy <= 32 && xx >= 1 && xx <= 32)
                val = hb[((h2*16 + ci) << 10) + ((yy-1) << 5) + (xx-1)];
            in_s[i] = val;
        }
        __syncthreads();
        for (int ci = 0; ci < 16; ci++) {
            ull pr[3][5];
            #pragma unroll
            for (int rr = 0; rr < 3; rr++) {
                const float* row = in_s + ci*PHI_CI + (y+rr)*36 + x0;
                float4 u03 = *(const float4*)row;
                float2 u45 = *(const float2*)(row + 4);
                pr[rr][0] = pack2(u03.x, u03.y);
                pr[rr][1] = pack2(u03.y, u03.z);
                pr[rr][2] = pack2(u03.z, u03.w);
                pr[rr][3] = pack2(u03.w, u45.x);
                pr[rr][4] = pack2(u45.x, u45.y);
            }
            #pragma unroll
            for (int k = 0; k < 4; k++) {
                const ull* wk = w2 + (size_t)(k*32 + h2*16 + ci)*9;
                ull a = accA[k], c2 = accB[k];
                #pragma unroll
                for (int rr = 0; rr < 3; rr++) {
                    ull w0 = wk[rr*3], w1 = wk[rr*3+1], wv2 = wk[rr*3+2];
                    a  = fma2(pr[rr][0], w0, a);
                    a  = fma2(pr[rr][1], w1, a);
                    a  = fma2(pr[rr][2], wv2, a);
                    c2 = fma2(pr[rr][2], w0, c2);
                    c2 = fma2(pr[rr][3], w1, c2);
                    c2 = fma2(pr[rr][4], wv2, c2);
                }
                accA[k] = a; accB[k] = c2;
            }
        }
        __syncthreads();
    }
    // writeback + stage updated tile for pooling
    #pragma unroll
    for (int k = 0; k < 4; k++) {
        float2 pa = unpack2(accA[k]);
        float2 pbv = unpack2(accB[k]);
        float conv[4] = {pa.x, pa.y, pbv.x, pbv.y};
        int co = cog*4 + k;
        #pragma unroll
        for (int q = 0; q < 4; q++) {
            int x = x0 + q;
            int gi = ((b*32 + co) << 10) + (y << 5) + x;
            float hval = g_h32[gi];
            float newv = g_frest[gi] - (0.5f*hval + 0.5f*conv[q]);
            g_frest[gi] = newv;
            pool[k*1024 + (y << 5) + x] = newv;
        }
    }
    __syncthreads();
    if (pn2 < 32) {
        int w = t >> 5, l = t & 31;
        for (int o = w; o < 4*pn22; o += 8) {
            int k = o / pn22, p = o - k*pn22;
            int ph = p / pn2, pw2 = p - ph*pn2;
            float acc = 0.f;
            for (int e = l; e < s22; e += 32) {
                int dy = e / s2, dx = e - dy*s2;
                acc += pool[k*1024 + ((ph*s2 + dy) << 5) + (pw2*s2 + dx)];
            }
            #pragma unroll
            for (int off = 16; off; off >>= 1)
                acc += __shfl_down_sync(~0u, acc, off);
            if (l == 0)
                g_r[(b*32 + cog*4 + k)*pn22 + p] = acc * invp;
        }
    }
}

// ================ hits for si=5 ================
__global__ void k_hits5() {
    for (int n = blockIdx.x*blockDim.x + threadIdx.x; n < 32768; n += gridDim.x*blockDim.x) {
        int idx = (int)(g_best[n] & 0xFFFull);
        atomicAdd(&g_hits[idx], 1.f);
    }
}

// ================ final: loss + perplexity ================
__global__ void k_final(float* __restrict__ out, int osz) {
    __shared__ float red[256];
    int t = threadIdx.x;
    red[t] = g_part[t] + g_part[t + 256]; __syncthreads();
    for (int o = 128; o > 0; o >>= 1) { if (t < o) red[t] += red[t+o]; __syncthreads(); }
    float S = red[0]; __syncthreads();
    float m = S / (float)NPIX;
    float h = 0.f;
    for (int k = 0; k < 16; k++) h += g_hits[t + k*256];
    red[t] = h; __syncthreads();
    for (int o = 128; o > 0; o >>= 1) { if (t < o) red[t] += red[t+o]; __syncthreads(); }
    float tot = red[0]; __syncthreads();
    float denom = fmaxf(tot, 1.f);
    float e = 0.f;
    for (int k = 0; k < 16; k++) {
        float p = g_hits[t + k*256] / denom;
        e += p * logf(p + 1e-10f);
    }
    red[t] = e; __syncthreads();
    for (int o = 128; o > 0; o >>= 1) { if (t < o) red[t] += red[t+o]; __syncthreads(); }
    if (t == 0) {
        float ent = red[0];
        float loss = 0.f;
        for (int si = 0; si < 6; si++) { loss = loss + 0.25f*m; loss = loss + m; }
        out[osz - 2] = loss;
        out[osz - 1] = expf(-ent);
    }
}

// ================ launcher ================
extern "C" void kernel_launch(void* const* d_in, const int* in_sizes, int n_in,
                              void* d_out, int out_size) {
    const float* f   = (const float*)d_in[0];
    const float* emb = (const float*)d_in[1];
    const float* pw  = (const float*)d_in[2];
    const float* pb  = (const float*)d_in[3];
    float* out = (float*)d_out;

    static int NBA = 0;
    if (NBA == 0) {
        int dev = 0; cudaGetDevice(&dev);
        int sms = 0;
        cudaDeviceGetAttribute(&sms, cudaDevAttrMultiProcessorCount, dev);
        if (sms <= 0) sms = 148;
        NBA = 2 * sms;
        cudaFuncSetAttribute(k_argmin, cudaFuncAttributeMaxDynamicSharedMemorySize, 82*1024);
        cudaFuncSetAttribute(k_phi,    cudaFuncAttributeMaxDynamicSharedMemorySize, 88*1024);
        cudaFuncSetAttribute(k_ups,    cudaFuncAttributeMaxDynamicSharedMemorySize, 16*1024);
    }

    const int pns[6]    = {1,2,4,8,16,32};
    const int phiSel[6] = {0,0,1,2,3,3};
    // per-scale: V-split VS, chunk=4096/VS, TC=min(chunk,512), 64-row groups G
    const int VSs[6]    = {128,128,32,64,16,4};

    k_prep<<<512, 256>>>((const float4*)f, (float4*)out, emb);

    for (int si = 0; si < 6; si++) {
        int pn = pns[si], pnpn = pn*pn, N = 32*pnpn;
        int VS = VSs[si], chunk = 4096 / VS;
        int TC = chunk < 512 ? chunk : 512;
        int mode, G, items;
        if (pn == 1) { mode = 0; G = 1; items = VS; }
        else {
            G = N / 64;
            items = G * VS;
            mode = (pn == 32) ? 2 : 1;
        }
        size_t smem = (size_t)TC*33*sizeof(float) + 8192 + 4096;
        int grid = items < NBA ? items : NBA;
        k_argmin<<<grid, 256, smem>>>(emb, pnpn, G, chunk, TC, items, mode);
        if (si < 5) {
            size_t us = (size_t)(4*pnpn + 4*pn*32 + 32*pn) * sizeof(float);
            k_ups<<<256, 256, us>>>(emb, pn, si);
            size_t ps = (size_t)(19584 + 2304 + 4) * sizeof(float);
            k_phi<<<256, 256, ps>>>(pw + phiSel[si]*9216, pb + phiSel[si]*32, pns[si+1]);
        }
    }
    k_hits5<<<128, 256>>>();
    k_final<<<1, 256>>>(out, out_size);
}

// round 10
// speedup vs baseline: 2.3366x; 1.0547x over previous
#include <cuda_runtime.h>
#include <math.h>
#include <float.h>

typedef unsigned long long ull;

#define NPIX (32*32*1024)
#define Vv 4096

// ---- static device scratch ----
__device__ float g_frest[NPIX];
__device__ float g_r[32*32*256];      // downsampled z, layout [(b*32+c)*pnpn + p]
__device__ float g_h32[NPIX];
__device__ float g_hits[Vv];
__device__ float g_esq[Vv];
__device__ float g_Mm[5][32][16];
__device__ float g_part[512];
__device__ ull   g_best[32768];

// ---- packed f32x2 helpers (FFMA2) ----
__device__ __forceinline__ ull pack2(float lo, float hi) {
    ull d;
    asm("mov.b64 %0, {%1, %2};" : "=l"(d)
        : "r"(__float_as_uint(lo)), "r"(__float_as_uint(hi)));
    return d;
}
__device__ __forceinline__ float2 unpack2(ull v) {
    unsigned int lo, hi;
    asm("mov.b64 {%0, %1}, %2;" : "=r"(lo), "=r"(hi) : "l"(v));
    return make_float2(__uint_as_float(lo), __uint_as_float(hi));
}
__device__ __forceinline__ ull fma2(ull a, ull b, ull c) {
    ull d;
    asm("fma.rn.f32x2 %0, %1, %2, %3;" : "=l"(d) : "l"(a), "l"(b), "l"(c));
    return d;
}
__device__ __forceinline__ ull add2(ull a, ull b) {
    ull d;
    asm("add.rn.f32x2 %0, %1, %2;" : "=l"(d) : "l"(a), "l"(b));
    return d;
}

__device__ __forceinline__ ull enc_key(float d, int idx) {
    unsigned u = __float_as_uint(d);
    u = (u & 0x80000000u) ? ~u : (u | 0x80000000u);
    return ((ull)u << 12) | (unsigned)idx;
}

// ================ prep ================
__global__ void __launch_bounds__(256) k_prep(const float4* __restrict__ f,
                                              float4* __restrict__ out4,
                                              const float* __restrict__ emb) {
    __shared__ float red[256];
    int t = threadIdx.x, blk = blockIdx.x;
    float s = 0.f;
    for (int i = blk*256 + t; i < NPIX/4; i += gridDim.x*256) {
        float4 v = f[i];
        ((float4*)g_frest)[i] = v;
        s = fmaf(v.x, v.x, fmaf(v.y, v.y, fmaf(v.z, v.z, fmaf(v.w, v.w, s))));
        out4[i] = make_float4(0.f, 0.f, 0.f, 0.f);
    }
    red[t] = s; __syncthreads();
    for (int o = 128; o > 0; o >>= 1) { if (t < o) red[t] += red[t+o]; __syncthreads(); }
    if (t == 0) g_part[blk] = red[0];

    {   // plane means for si=0
        int gw = blk*8 + (t >> 5), l = t & 31;
        if (gw < 1024) {
            const float4* pf = f + gw*256;
            float acc = 0.f;
            for (int i = l; i < 256; i += 32) {
                float4 v = pf[i]; acc += (v.x + v.y) + (v.z + v.w);
            }
            #pragma unroll
            for (int off = 16; off; off >>= 1) acc += __shfl_down_sync(~0u, acc, off);
            if (l == 0) g_r[gw] = acc * (1.f/1024.f);
        }
    }
    for (int v = blk*256 + t; v < Vv; v += gridDim.x*256) {
        g_hits[v] = 0.f;
        const float* e = emb + v*32;
        float acc = 0.f;
        #pragma unroll
        for (int c = 0; c < 32; c++) acc += e[c]*e[c];
        g_esq[v] = acc;
    }
    if (blk == 0) {
        if (t < 160) {
            int si = t >> 5, r = t & 31;
            const int pns5[5] = {1,2,4,8,16};
            int pn = pns5[si];
            for (int j = 0; j < 16; j++) g_Mm[si][r][j] = 0.f;
            double scale = (double)pn / 32.0;
            double x = (r + 0.5)*scale - 0.5;
            double x0 = floor(x);
            double tt = x - x0;
            int ix0 = (int)x0;
            const double a = -0.75;
            for (int j = -1; j <= 2; j++) {
                double d = fabs(tt - (double)j);
                double w;
                if (d < 1.0)      w = (a+2.0)*d*d*d - (a+3.0)*d*d + 1.0;
                else if (d < 2.0) w = a*d*d*d - 5.0*a*d*d + 8.0*a*d - 4.0*a;
                else              w = 0.0;
                int col = ix0 + j;
                col = col < 0 ? 0 : (col > pn-1 ? pn-1 : col);
                g_Mm[si][r][col] = (float)((double)g_Mm[si][r][col] + w);
            }
        }
        if (t < 32) g_best[t] = ~0ull;
    }
}

// ================ argmin (unchanged from R8) ================
__global__ void __launch_bounds__(256, 2) k_argmin(const float* __restrict__ emb,
                                                   int pnpn, int G, int chunk,
                                                   int TC, int items, int mode) {
    extern __shared__ float sm[];
    float4* es4   = (float4*)sm;
    float*  esq_s = sm + (size_t)TC*32;
    ull*    z2t   = (ull*)(sm + (size_t)TC*33);
    float*  sdA   = (float*)(z2t + 1024);
    float*  sdB   = sdA + 256;
    int*    svA   = (int*)(sdB + 256);
    int*    svB   = svA + 256;
    int t = threadIdx.x;

    if (mode == 0) {
        for (int item = blockIdx.x; item < items; item += gridDim.x) {
            __syncthreads();
            {
                int r = t >> 3, cq = (t & 7)*4;
                float zc[4];
                #pragma unroll
                for (int q = 0; q < 4; q++) zc[q] = g_r[r*32 + cq + q];
                int i0 = cq >> 1;
                z2t[i0*32 + r]     = pack2(zc[0], zc[1]);
                z2t[(i0+1)*32 + r] = pack2(zc[2], zc[3]);
            }
            __syncthreads();
            int w = t >> 5, l = t & 31;
            ull zp[16];
            #pragma unroll
            for (int i = 0; i < 16; i++) zp[i] = z2t[i*32 + l];
            float best = FLT_MAX; int bv = 0;
            int v0 = item*chunk;
            for (int t0 = v0; t0 < v0 + chunk; t0 += TC) {
                __syncthreads();
                const float4* eg = (const float4*)(emb + (size_t)t0*32);
                for (int i = t; i < TC*8; i += 256) es4[i] = eg[i];
                for (int i = t; i < TC;   i += 256) esq_s[i] = g_esq[t0 + i];
                __syncthreads();
                for (int v = w; v < TC; v += 8) {
                    const ulonglong2* evp = (const ulonglong2*)(es4 + v*8);
                    ull a0 = 0ull, a1 = 0ull;
                    #pragma unroll
                    for (int i = 0; i < 8; i++) {
                        ulonglong2 q = evp[i];
                        a0 = fma2(zp[2*i],   q.x, a0);
                        a1 = fma2(zp[2*i+1], q.y, a1);
                    }
                    float2 pq = unpack2(add2(a0, a1));
                    float dist = fmaf(-2.f, pq.x + pq.y, esq_s[v]);
                    if (dist < best) { best = dist; bv = t0 + v; }
                }
            }
            sdA[t] = best; svA[t] = bv;
            __syncthreads();
            if (w == 0) {
                float bb = sdA[l]; int vv = svA[l];
                #pragma unroll
                for (int k = 1; k < 8; k++) {
                    float d2 = sdA[k*32 + l]; int v2 = svA[k*32 + l];
                    if (d2 < bb || (d2 == bb && v2 < vv)) { bb = d2; vv = v2; }
                }
                atomicMin(&g_best[l], enc_key(bb, vv));
            }
        }
    } else {
        for (int item = blockIdx.x; item < items; item += gridDim.x) {
            __syncthreads();
            int g = item % G, vc = item / G;
            {
                int r = t >> 2, cq = (t & 3)*8;
                int n = g*64 + r;
                int b = n / pnpn, p = n - b*pnpn;
                float zc[8];
                if (mode == 2) {
                    #pragma unroll
                    for (int q = 0; q < 8; q++)
                        zc[q] = g_frest[((b*32 + cq + q) << 10) + p];
                } else {
                    #pragma unroll
                    for (int q = 0; q < 8; q++)
                        zc[q] = g_r[(b*32 + cq + q)*pnpn + p];
                }
                int i0 = cq >> 1;
                #pragma unroll
                for (int j = 0; j < 4; j++)
                    z2t[(i0+j)*64 + r] = pack2(zc[2*j], zc[2*j+1]);
            }
            __syncthreads();
            int w = t >> 5, l = t & 31;
            ull zpA[16], zpB[16];
            #pragma unroll
            for (int i = 0; i < 16; i++) {
                zpA[i] = z2t[i*64 + l];
                zpB[i] = z2t[i*64 + 32 + l];
            }
            float bestA = FLT_MAX, bestB = FLT_MAX; int bvA = 0, bvB = 0;
            int v0 = vc*chunk;
            for (int t0 = v0; t0 < v0 + chunk; t0 += TC) {
                __syncthreads();
                const float4* eg = (const float4*)(emb + (size_t)t0*32);
                for (int i = t; i < TC*8; i += 256) es4[i] = eg[i];
                for (int i = t; i < TC;   i += 256) esq_s[i] = g_esq[t0 + i];
                __syncthreads();
                for (int v = w; v < TC; v += 8) {
                    const ulonglong2* evp = (const ulonglong2*)(es4 + v*8);
                    ull a0 = 0ull, a1 = 0ull, b0 = 0ull, b1 = 0ull;
                    #pragma unroll
                    for (int i = 0; i < 8; i++) {
                        ulonglong2 q = evp[i];
                        a0 = fma2(zpA[2*i],   q.x, a0);
                        a1 = fma2(zpA[2*i+1], q.y, a1);
                        b0 = fma2(zpB[2*i],   q.x, b0);
                        b1 = fma2(zpB[2*i+1], q.y, b1);
                    }
                    float2 pa = unpack2(add2(a0, a1));
                    float dA = fmaf(-2.f, pa.x + pa.y, esq_s[v]);
                    float2 pbv = unpack2(add2(b0, b1));
                    float dB = fmaf(-2.f, pbv.x + pbv.y, esq_s[v]);
                    if (dA < bestA) { bestA = dA; bvA = t0 + v; }
                    if (dB < bestB) { bestB = dB; bvB = t0 + v; }
                }
            }
            sdA[t] = bestA; svA[t] = bvA; sdB[t] = bestB; svB[t] = bvB;
            __syncthreads();
            int w2i = t >> 5, l2 = t & 31;
            if (w2i == 0) {
                float bb = sdA[l2]; int vv = svA[l2];
                #pragma unroll
                for (int k = 1; k < 8; k++) {
                    float d2 = sdA[k*32 + l2]; int v2 = svA[k*32 + l2];
                    if (d2 < bb || (d2 == bb && v2 < vv)) { bb = d2; vv = v2; }
                }
                atomicMin(&g_best[g*64 + l2], enc_key(bb, vv));
            } else if (w2i == 1) {
                float bb = sdB[l2]; int vv = svB[l2];
                #pragma unroll
                for (int k = 1; k < 8; k++) {
                    float d2 = sdB[k*32 + l2]; int v2 = svB[k*32 + l2];
                    if (d2 < bb || (d2 == bb && v2 < vv)) { bb = d2; vv = v2; }
                }
                atomicMin(&g_best[g*64 + 32 + l2], enc_key(bb, vv));
            }
        }
    }
}

// ================ ups (unchanged) ================
__global__ void __launch_bounds__(256) k_ups(const float* __restrict__ emb, int pn, int sidx) {
    extern __shared__ float sm[];
    int pnpn = pn * pn;
    float* hq  = sm;
    float* tmp = hq + 4*pnpn;
    float* Ms  = tmp + 4*pn*32;
    int b = blockIdx.x >> 3, cg = blockIdx.x & 7, t = threadIdx.x;
    for (int i = t; i < 32*pn; i += 256) Ms[i] = g_Mm[sidx][i/pn][i%pn];
    if (cg == 0) {
        for (int j = t; j < pnpn; j += 256) {
            int idx = (int)(g_best[b*pnpn + j] & 0xFFFull);
            atomicAdd(&g_hits[idx], 1.f);
        }
    }
    for (int j = t; j < 4*pnpn; j += 256) {
        int c = j / pnpn, p = j - c*pnpn;
        int idx = (int)(g_best[b*pnpn + p] & 0xFFFull);
        hq[j] = emb[(size_t)idx*32 + cg*4 + c];
    }
    __syncthreads();
    for (int j = t; j < 4*pn*32; j += 256) {
        int c = j / (pn*32); int rem = j - c*(pn*32);
        int h = rem >> 5; int X = rem & 31;
        float acc = 0.f;
        for (int wv = 0; wv < pn; wv++)
            acc = fmaf(Ms[X*pn + wv], hq[c*pnpn + h*pn + wv], acc);
        tmp[j] = acc;
    }
    __syncthreads();
    for (int j = t; j < 4096; j += 256) {
        int c = j >> 10, Y = (j >> 5) & 31, X = j & 31;
        float acc = 0.f;
        for (int hv = 0; hv < pn; hv++)
            acc = fmaf(Ms[Y*pn + hv], tmp[(c*pn + hv)*32 + X], acc);
        g_h32[((b*32 + cg*4 + c) << 10) + (Y << 5) + X] = acc;
    }
}

// ================ phi: 512 threads, 8 out-channels/block, grid 128 ================
#define PHI_CI 1224   // 34*36
__global__ void __launch_bounds__(512, 2) k_phi(const float* __restrict__ wgt,
                                                const float* __restrict__ bias,
                                                int pn2) {
    extern __shared__ float sm[];
    float* in_s = sm;                      // 16*1224 = 19584 floats
    ull*   w2   = (ull*)(sm + 19584);      // 2304 ull (8 co x 32 ci x 9)
    int blk = blockIdx.x;
    int b = blk >> 2, cg8 = blk & 3, t = threadIdx.x;
    int pn22 = pn2*pn2;
    int s2 = 32 / pn2, s22 = s2*s2;
    float invp = 1.f / (float)s22;

    // reset g_best for next scale
    for (int i = blk*512 + t; i < 32*pn22; i += gridDim.x*512) g_best[i] = ~0ull;

    // weights (packed for pixel-pair fma)
    for (int i = t; i < 2304; i += 512) {
        float wv = wgt[cg8*2304 + i]; w2[i] = pack2(wv, wv);
    }

    // zero halo once (interior overwritten per half)
    for (int i = t; i < 3200; i += 512) {
        int ci = i / 200, r = i - ci*200;
        int yy, xx;
        if (r < 36)      { yy = 0;       xx = r; }
        else if (r < 72) { yy = 33;      xx = r - 36; }
        else if (r < 104){ yy = r - 71;  xx = 0; }
        else { int q = r - 104; xx = 33 + (q >> 5); yy = 1 + (q & 31); }
        in_s[ci*PHI_CI + yy*36 + xx] = 0.f;
    }

    int kk = t >> 8, tt = t & 255;
    int y = tt >> 3, x0 = (tt & 7)*4;
    ull accA[4], accB[4];
    #pragma unroll
    for (int k = 0; k < 4; k++) {
        // bias straight from global (race-free; was the R9 bug via unsynced smem)
        float bv = bias[cg8*8 + kk*4 + k];
        ull bb = pack2(bv, bv); accA[k] = bb; accB[k] = bb;
    }
    const float* hb = g_h32 + (size_t)b*32768;

    for (int h2 = 0; h2 < 2; h2++) {
        __syncthreads();
        for (int i = t; i < 16384; i += 512) {
            int ci = i >> 10, p = i & 1023;
            in_s[ci*PHI_CI + ((p >> 5) + 1)*36 + (p & 31) + 1]
                = hb[((h2*16 + ci) << 10) + p];
        }
        __syncthreads();
        for (int ci = 0; ci < 16; ci++) {
            const float* pl = in_s + ci*PHI_CI;
            #pragma unroll
            for (int rr = 0; rr < 3; rr++) {
                const float* row = pl + (y + rr)*36 + x0;   // 16B aligned
                float4 u03 = *(const float4*)row;
                float2 u45 = *(const float2*)(row + 4);
                ull p0 = pack2(u03.x, u03.y);
                ull p1 = pack2(u03.y, u03.z);
                ull p2 = pack2(u03.z, u03.w);
                ull p3 = pack2(u03.w, u45.x);
                ull p4 = pack2(u45.x, u45.y);
                #pragma unroll
                for (int k = 0; k < 4; k++) {
                    const ull* wk = w2 + (size_t)((kk*4 + k)*288 + (h2*16 + ci)*9 + rr*3);
                    ull w0 = wk[0], w1 = wk[1], wv2 = wk[2];
                    ull a = accA[k], c2 = accB[k];
                    a  = fma2(p0, w0, a);  a  = fma2(p1, w1, a);  a  = fma2(p2, wv2, a);
                    c2 = fma2(p2, w0, c2); c2 = fma2(p3, w1, c2); c2 = fma2(p4, wv2, c2);
                    accA[k] = a; accB[k] = c2;
                }
            }
        }
    }
    __syncthreads();   // done reading in_s; reuse as pool stage

    #pragma unroll
    for (int k = 0; k < 4; k++) {
        float2 pa = unpack2(accA[k]);
        float2 pbv = unpack2(accB[k]);
        float conv[4] = {pa.x, pa.y, pbv.x, pbv.y};
        int kl = kk*4 + k;
        int co = cg8*8 + kl;
        #pragma unroll
        for (int q = 0; q < 4; q++) {
            int x = x0 + q;
            int gi = ((b*32 + co) << 10) + (y << 5) + x;
            float hval = g_h32[gi];
            float newv = g_frest[gi] - (0.5f*hval + 0.5f*conv[q]);
            g_frest[gi] = newv;
            in_s[kl*1024 + (y << 5) + x] = newv;
        }
    }
    __syncthreads();
    if (pn2 < 32) {
        int w = t >> 5, l = t & 31;
        for (int o = w; o < 8*pn22; o += 16) {
            int kl = o / pn22, p = o - kl*pn22;
            int ph = p / pn2, pw2 = p - ph*pn2;
            float acc = 0.f;
            for (int e = l; e < s22; e += 32) {
                int dy = e / s2, dx = e - dy*s2;
                acc += in_s[kl*1024 + ((ph*s2 + dy) << 5) + (pw2*s2 + dx)];
            }
            #pragma unroll
            for (int off = 16; off; off >>= 1)
                acc += __shfl_down_sync(~0u, acc, off);
            if (l == 0)
                g_r[(b*32 + cg8*8 + kl)*pn22 + p] = acc * invp;
        }
    }
}

// ================ hits for si=5 ================
__global__ void k_hits5() {
    for (int n = blockIdx.x*blockDim.x + threadIdx.x; n < 32768; n += gridDim.x*blockDim.x) {
        int idx = (int)(g_best[n] & 0xFFFull);
        atomicAdd(&g_hits[idx], 1.f);
    }
}

// ================ final ================
__global__ void k_final(float* __restrict__ out, int osz) {
    __shared__ float red[256];
    int t = threadIdx.x;
    red[t] = g_part[t] + g_part[t + 256]; __syncthreads();
    for (int o = 128; o > 0; o >>= 1) { if (t < o) red[t] += red[t+o]; __syncthreads(); }
    float S = red[0]; __syncthreads();
    float m = S / (float)NPIX;
    float h = 0.f;
    for (int k = 0; k < 16; k++) h += g_hits[t + k*256];
    red[t] = h; __syncthreads();
    for (int o = 128; o > 0; o >>= 1) { if (t < o) red[t] += red[t+o]; __syncthreads(); }
    float tot = red[0]; __syncthreads();
    float denom = fmaxf(tot, 1.f);
    float e = 0.f;
    for (int k = 0; k < 16; k++) {
        float p = g_hits[t + k*256] / denom;
        e += p * logf(p + 1e-10f);
    }
    red[t] = e; __syncthreads();
    for (int o = 128; o > 0; o >>= 1) { if (t < o) red[t] += red[t+o]; __syncthreads(); }
    if (t == 0) {
        float ent = red[0];
        float loss = 0.f;
        for (int si = 0; si < 6; si++) { loss = loss + 0.25f*m; loss = loss + m; }
        out[osz - 2] = loss;
        out[osz - 1] = expf(-ent);
    }
}

// ================ launcher ================
extern "C" void kernel_launch(void* const* d_in, const int* in_sizes, int n_in,
                              void* d_out, int out_size) {
    const float* f   = (const float*)d_in[0];
    const float* emb = (const float*)d_in[1];
    const float* pw  = (const float*)d_in[2];
    const float* pb  = (const float*)d_in[3];
    float* out = (float*)d_out;

    static int NBA = 0;
    if (NBA == 0) {
        int dev = 0; cudaGetDevice(&dev);
        int sms = 0;
        cudaDeviceGetAttribute(&sms, cudaDevAttrMultiProcessorCount, dev);
        if (sms <= 0) sms = 148;
        NBA = 2 * sms;
        cudaFuncSetAttribute(k_argmin, cudaFuncAttributeMaxDynamicSharedMemorySize, 82*1024);
        cudaFuncSetAttribute(k_phi,    cudaFuncAttributeMaxDynamicSharedMemorySize, 98*1024);
        cudaFuncSetAttribute(k_ups,    cudaFuncAttributeMaxDynamicSharedMemorySize, 16*1024);
    }

    const int pns[6]    = {1,2,4,8,16,32};
    const int phiSel[6] = {0,0,1,2,3,3};
    const int VSs[6]    = {128,128,32,64,16,4};

    k_prep<<<512, 256>>>((const float4*)f, (float4*)out, emb);

    for (int si = 0; si < 6; si++) {
        int pn = pns[si], pnpn = pn*pn, N = 32*pnpn;
        int VS = VSs[si], chunk = 4096 / VS;
        int TC = chunk < 512 ? chunk : 512;
        int mode, G, items;
        if (pn == 1) { mode = 0; G = 1; items = VS; }
        else {
            G = N / 64;
            items = G * VS;
            mode = (pn == 32) ? 2 : 1;
        }
        size_t smem = (size_t)TC*33*sizeof(float) + 8192 + 4096;
        int grid = items < NBA ? items : NBA;
        k_argmin<<<grid, 256, smem>>>(emb, pnpn, G, chunk, TC, items, mode);
        if (si < 5) {
            size_t us = (size_t)(4*pnpn + 4*pn*32 + 32*pn) * sizeof(float);
            k_ups<<<256, 256, us>>>(emb, pn, si);
            size_t ps = (size_t)(19584 + 4608) * sizeof(float);
            k_phi<<<128, 512, ps>>>(pw + phiSel[si]*9216, pb + phiSel[si]*32, pns[si+1]);
        }
    }
    k_hits5<<<128, 256>>>();
    k_final<<<1, 256>>>(out, out_size);
}